// round 12
// baseline (speedup 1.0000x reference)
#include <cuda_runtime.h>
#include <cstdint>

#define B_TOT   16
#define CIN     64
#define COUT    64
#define S_LEN   1024
#define KW      3
#define STILE   32
#define POSN    34              // 32 + halo
#define POSNP   36              // padded pos (keeps LDS.64 lanes conflict-free)
#define BH      8               // batches per block
#define BPAIRS  (BH / 2)        // 4 f32x2 batch-pairs
#define OTILE   4               // outputs per thread
#define OGN     8               // o-groups per c-half
#define OBLK    (OGN * OTILE)   // 32 outputs per block
#define CHALF   (CIN / 2)       // 32 c per warp-half
#define NTHREADS 512            // 16 warps: [c-half][o-group]
#define SK      (S_LEN * KW)            // per-c weight stride (floats)
#define OCS     (CIN * S_LEN * KW)      // per-o weight stride (floats)
#define CROW    (BPAIRS * POSNP)        // u64 per c row = 144
#define SMEM_U64 (CIN * CROW)           // 9216 u64 = 73728 B

typedef unsigned long long u64;

// d = a * b + d, lanewise on two packed f32 (sm_103a FFMA2).
#define FFMA2(d, a, b) \
    asm("fma.rn.f32x2 %0, %1, %2, %0;" : "+l"(d) : "l"(a), "l"(b))
#define ADD2(d, a, b) \
    asm("add.rn.f32x2 %0, %1, %2;" : "=l"(d) : "l"(a), "l"(b))
// Duplicate one f32 into both lanes of an f32x2.
#define PACKDUP(d, f) \
    asm("mov.b64 %0, {%1, %1};" : "=l"(d) : "r"(__float_as_uint(f)))

__global__ void __launch_bounds__(NTHREADS)
locon1d_kernel(const float* __restrict__ X,     // (B, Cin, S)
               const float* __restrict__ W,     // (Cout, Cin, S, K)
               const float* __restrict__ Bias,  // (Cout, S)
               float* __restrict__ Out)         // (B, Cout, S)
{
    // x tile as packed pairs: u64 element [c][bp][p] = {x[2bp][p], x[2bp+1][p]}
    extern __shared__ u64 shx2[];

    const int s0     = blockIdx.x * STILE;
    const int o0base = blockIdx.y * OBLK;
    const int b0     = blockIdx.z * BH;
    const int tid    = threadIdx.x;
    const int sl     = tid & 31;          // lane = consecutive s
    const int wid    = tid >> 5;          // 0..15
    const int og     = wid & 7;           // o-group
    const int ch     = wid >> 3;          // c-half: 0 or 1

    // ── Input tile fill: warp -> (batch bf, c-half chf). Scalar STS into the
    //    interleaved pair layout (2-way bank phase, fill is tiny vs mainloop).
    {
        const int  bf   = wid >> 1;                // batch this warp fills (0..7)
        const int  chf  = wid & 1;                 // c-half this warp fills
        const float* xb = X + ((size_t)(b0 + bf) * CIN + chf * CHALF) * S_LEN;
        float* shb = (float*)shx2
                   + (((size_t)(chf * CHALF) * BPAIRS + (bf >> 1)) * POSNP) * 2
                   + (bf & 1);
        const int  sg  = s0 - 1 + sl;
        const bool m1  = (unsigned)sg < (unsigned)S_LEN;
        const int  sg2 = s0 + 31 + sl;
        const bool m2  = (sl < 2) && ((unsigned)sg2 < (unsigned)S_LEN);
        #pragma unroll 4
        for (int cc = 0; cc < CHALF; cc++) {
            shb[(size_t)cc * (CROW * 2) + sl * 2] =
                m1 ? xb[(size_t)cc * S_LEN + sg] : 0.0f;
            if (sl < 2)
                shb[(size_t)cc * (CROW * 2) + (32 + sl) * 2] =
                    m2 ? xb[(size_t)cc * S_LEN + sg2] : 0.0f;
        }
    }
    __syncthreads();

    const int s  = s0 + sl;
    const int o0 = o0base + og * OTILE;

    // acc2[j][bp]: 4 outputs x 4 batch-pairs = 16 packed (32 regs).
    u64 acc2[OTILE][BPAIRS];
    #pragma unroll
    for (int j = 0; j < OTILE; j++) {
        u64 bp2;
        if (ch == 0) { PACKDUP(bp2, Bias[(size_t)(o0 + j) * S_LEN + s]); }
        else         { bp2 = 0ull; }
        #pragma unroll
        for (int p = 0; p < BPAIRS; p++) acc2[j][p] = bp2;
    }

    const float* wbase = W + (size_t)o0 * OCS
                           + (size_t)(ch * CHALF) * SK
                           + (size_t)s * KW;
    const u64* xc = shx2 + (size_t)(ch * CHALF) * CROW + sl;

    #pragma unroll 2
    for (int ci = 0; ci < CHALF; ci++) {
        // 12 scalar weight LDGs (lanes = consecutive s, 384B/warp), packed dup.
        const float* wc = wbase + (size_t)ci * SK;
        u64 wp[OTILE][KW];
        #pragma unroll
        for (int j = 0; j < OTILE; j++) {
            const float* wj = wc + (size_t)j * OCS;
            #pragma unroll
            for (int k = 0; k < KW; k++) { PACKDUP(wp[j][k], wj[k]); }
        }

        const u64* xrow = xc + (size_t)ci * CROW;
        #pragma unroll
        for (int p = 0; p < BPAIRS; p++) {
            // one LDS.64 per tap: {x[2p], x[2p+1]}, conflict-free
            const u64 x0 = xrow[p * POSNP + 0];
            const u64 x1 = xrow[p * POSNP + 1];
            const u64 x2 = xrow[p * POSNP + 2];
            #pragma unroll
            for (int j = 0; j < OTILE; j++) {
                FFMA2(acc2[j][p], wp[j][0], x0);
                FFMA2(acc2[j][p], wp[j][1], x1);
                FFMA2(acc2[j][p], wp[j][2], x2);
            }
        }
    }

    // ── Cross-half reduction through smem (x tile dead; reuse as u64 buffer).
    __syncthreads();
    const int t2 = og * 32 + sl;            // 0..255 within a c-half
    if (ch == 1) {
        #pragma unroll
        for (int j = 0; j < OTILE; j++)
            #pragma unroll
            for (int p = 0; p < BPAIRS; p++)
                shx2[(j * BPAIRS + p) * 256 + t2] = acc2[j][p];
    }
    __syncthreads();
    if (ch == 0) {
        #pragma unroll
        for (int j = 0; j < OTILE; j++) {
            #pragma unroll
            for (int p = 0; p < BPAIRS; p++) {
                u64 v;
                ADD2(v, acc2[j][p], shx2[(j * BPAIRS + p) * 256 + t2]);
                const float lo = __uint_as_float((unsigned)(v & 0xffffffffull));
                const float hi = __uint_as_float((unsigned)(v >> 32));
                // lanes = consecutive s -> coalesced 128B stores
                Out[((size_t)(b0 + 2 * p + 0) * COUT + (o0 + j)) * S_LEN + s] = lo;
                Out[((size_t)(b0 + 2 * p + 1) * COUT + (o0 + j)) * S_LEN + s] = hi;
            }
        }
    }
}

extern "C" void kernel_launch(void* const* d_in, const int* in_sizes, int n_in,
                              void* d_out, int out_size) {
    const float* x    = (const float*)d_in[0];
    const float* w    = (const float*)d_in[1];
    const float* bias = (const float*)d_in[2];
    float* out        = (float*)d_out;

    const int smem_bytes = SMEM_U64 * (int)sizeof(u64);  // 73728 B > 48K -> opt-in
    cudaFuncSetAttribute(locon1d_kernel,
                         cudaFuncAttributeMaxDynamicSharedMemorySize, smem_bytes);

    dim3 grid(S_LEN / STILE, COUT / OBLK, B_TOT / BH);  // (32, 2, 2) = 128 blocks
    locon1d_kernel<<<grid, NTHREADS, smem_bytes>>>(x, w, bias, out);
}